// round 3
// baseline (speedup 1.0000x reference)
#include <cuda_runtime.h>
#include <cuda_bf16.h>
#include <math.h>

#define BSZ 2
#define SEQL 1024
#define DMODEL 1024
#define DINNER 2048
#define DSTATE 16
#define DTRANK 64
#define NROWS (BSZ * SEQL)          // 2048 token rows
#define DBLW 96                     // dt_rank + 2*d_state

// ---------------- scratch (device globals; no allocation allowed) -------------
__device__ float g_xz[2][(size_t)NROWS * 2 * DINNER];   // in_proj output (xi | z)
__device__ float g_xc[2][(size_t)NROWS * DINNER];       // conv+silu output
__device__ float g_dbl[2][(size_t)NROWS * DBLW];        // x_proj output (dt|B|C)
__device__ float g_delta[2][(size_t)NROWS * DINNER];    // softplus(dt@dt_w + b)
__device__ float g_y[2][(size_t)NROWS * DINNER];        // gated scan output
__device__ float g_cat[(size_t)NROWS * 2 * DMODEL];     // [out_f | out_b]

// ---------------- generic SGEMM: C[m,n] = sum_k A[m,k] * W[n,k] ---------------
// A: M x K row-major (lda), W: N x K row-major (ldb), C: M x N (ldc).
// mode 0: plain store. mode 1: softplus(acc + bias[n]).
#define BM 128
#define BN 128
#define BKK 8

__global__ __launch_bounds__(256, 2)
void sgemm_nt(const float* __restrict__ A, const float* __restrict__ B,
              float* __restrict__ C, int M, int N, int K,
              int lda, int ldb, int ldc,
              const float* __restrict__ bias, int mode)
{
    __shared__ float As[BKK][BM];
    __shared__ float Bs[BKK][BN];

    const int tid = threadIdx.x;
    const int bm = blockIdx.y * BM;
    const int bn = blockIdx.x * BN;
    const int tx = tid & 15;          // 0..15 (n tiles)
    const int ty = tid >> 4;          // 0..15 (m tiles)

    const int lrow = tid >> 1;        // 0..127
    const int lcol = (tid & 1) * 4;   // 0 or 4

    const float* Aptr = A + (size_t)(bm + lrow) * lda + lcol;
    const int brow = bn + lrow;
    const float* Bptr = B + (size_t)brow * ldb + lcol;
    const bool bvalid = (brow < N);

    float acc[8][8];
#pragma unroll
    for (int i = 0; i < 8; i++)
#pragma unroll
        for (int j = 0; j < 8; j++) acc[i][j] = 0.f;

    for (int kk = 0; kk < K; kk += BKK) {
        float4 av = *(const float4*)(Aptr + kk);
        float4 bv = make_float4(0.f, 0.f, 0.f, 0.f);
        if (bvalid) bv = *(const float4*)(Bptr + kk);

        As[lcol + 0][lrow] = av.x;
        As[lcol + 1][lrow] = av.y;
        As[lcol + 2][lrow] = av.z;
        As[lcol + 3][lrow] = av.w;
        Bs[lcol + 0][lrow] = bv.x;
        Bs[lcol + 1][lrow] = bv.y;
        Bs[lcol + 2][lrow] = bv.z;
        Bs[lcol + 3][lrow] = bv.w;
        __syncthreads();

#pragma unroll
        for (int c = 0; c < BKK; ++c) {
            float4 a0 = *(const float4*)&As[c][ty * 8];
            float4 a1 = *(const float4*)&As[c][ty * 8 + 4];
            float4 b0 = *(const float4*)&Bs[c][tx * 8];
            float4 b1 = *(const float4*)&Bs[c][tx * 8 + 4];
            float ra[8] = {a0.x, a0.y, a0.z, a0.w, a1.x, a1.y, a1.z, a1.w};
            float rb[8] = {b0.x, b0.y, b0.z, b0.w, b1.x, b1.y, b1.z, b1.w};
#pragma unroll
            for (int i = 0; i < 8; i++)
#pragma unroll
                for (int j = 0; j < 8; j++)
                    acc[i][j] = fmaf(ra[i], rb[j], acc[i][j]);
        }
        __syncthreads();
    }

#pragma unroll
    for (int i = 0; i < 8; i++) {
        int m = bm + ty * 8 + i;
        if (m >= M) continue;
#pragma unroll
        for (int j = 0; j < 8; j++) {
            int n = bn + tx * 8 + j;
            if (n >= N) continue;
            float v = acc[i][j];
            if (mode == 1) {
                v += bias[n];
                v = (v > 20.f) ? v : log1pf(expf(v));   // softplus
            }
            C[(size_t)m * ldc + n] = v;
        }
    }
}

// ---------------- depthwise causal conv (d_conv=4) + SiLU ---------------------
// rev=0: xc[l] = silu(b + sum_k w[k]*xi[l-3+k])   (causal)
// rev=1: xc[l] = silu(b + sum_k w[k]*xi[l+3-k])   (anti-causal = bwd direction)
__global__ void conv_silu_kernel(const float* __restrict__ xz,
                                 const float* __restrict__ w,
                                 const float* __restrict__ bias,
                                 float* __restrict__ xc, int rev)
{
    int idx = blockIdx.x * blockDim.x + threadIdx.x;
    if (idx >= NROWS * DINNER) return;
    int e = idx % DINNER;
    int row = idx / DINNER;           // b*SEQL + l
    int l = row % SEQL;
    int b = row / SEQL;

    float accv = bias[e];
#pragma unroll
    for (int k = 0; k < 4; k++) {
        int li = rev ? (l + 3 - k) : (l - 3 + k);
        if (li >= 0 && li < SEQL)
            accv = fmaf(w[e * 4 + k],
                        xz[((size_t)(b * SEQL + li)) * (2 * DINNER) + e], accv);
    }
    float s = accv / (1.f + expf(-accv));   // silu
    xc[(size_t)row * DINNER + e] = s;
}

// ---------------- selective scan (+ skip + gate), one thread per (b,e) --------
__global__ __launch_bounds__(128)
void scan_kernel(const float* __restrict__ delta, const float* __restrict__ xc,
                 const float* __restrict__ dbl, const float* __restrict__ xz,
                 const float* __restrict__ A_log, const float* __restrict__ Dp,
                 float* __restrict__ y, int rev)
{
    const int e = blockIdx.x * blockDim.x + threadIdx.x;   // 0..2047
    const int b = blockIdx.y;

    float Av[DSTATE];
#pragma unroll
    for (int n = 0; n < DSTATE; n++) Av[n] = -expf(A_log[e * DSTATE + n]);

    // Detect A_n == (n+1)*A_0 structure (true for this problem's A_log) so
    // exp(delta*A_n) can be a power chain of one exp. Warp-uniform branch;
    // generic fallback keeps correctness if structure ever differs.
    bool structured = true;
#pragma unroll
    for (int n = 0; n < DSTATE; n++)
        structured = structured &&
            (fabsf(Av[n] - (float)(n + 1) * Av[0]) <= 1e-5f * fabsf(Av[n]) + 1e-7f);
    structured = __all_sync(0xffffffffu, structured);

    const float Dd = Dp[e];
    float h[DSTATE];
#pragma unroll
    for (int n = 0; n < DSTATE; n++) h[n] = 0.f;

    for (int t = 0; t < SEQL; t++) {
        const int l = rev ? (SEQL - 1 - t) : t;
        const size_t row = (size_t)b * SEQL + l;

        const float dlt = delta[row * DINNER + e];
        const float xcv = xc[row * DINNER + e];
        const float zz  = xz[row * (2 * DINNER) + DINNER + e];

        const float4* bc = (const float4*)(dbl + row * DBLW + DTRANK);
        float4 B0 = bc[0], B1 = bc[1], B2 = bc[2], B3 = bc[3];
        float4 C0 = bc[4], C1 = bc[5], C2 = bc[6], C3 = bc[7];
        float Bv[16] = {B0.x, B0.y, B0.z, B0.w, B1.x, B1.y, B1.z, B1.w,
                        B2.x, B2.y, B2.z, B2.w, B3.x, B3.y, B3.z, B3.w};
        float Cv[16] = {C0.x, C0.y, C0.z, C0.w, C1.x, C1.y, C1.z, C1.w,
                        C2.x, C2.y, C2.z, C2.w, C3.x, C3.y, C3.z, C3.w};

        const float du = dlt * xcv;
        float yacc = 0.f;

        if (structured) {
            const float e1 = __expf(dlt * Av[0]);
            float p = e1;
#pragma unroll
            for (int n = 0; n < DSTATE; n++) {
                h[n] = fmaf(p, h[n], du * Bv[n]);
                yacc = fmaf(h[n], Cv[n], yacc);
                p *= e1;
            }
        } else {
#pragma unroll
            for (int n = 0; n < DSTATE; n++) {
                float dA = __expf(dlt * Av[n]);
                h[n] = fmaf(dA, h[n], du * Bv[n]);
                yacc = fmaf(h[n], Cv[n], yacc);
            }
        }

        float yv = fmaf(xcv, Dd, yacc);                 // + skip
        float sz = zz / (1.f + __expf(-zz));            // silu(z)
        y[row * DINNER + e] = yv * sz;                  // gate
    }
}

// ------------------------------- host launch ----------------------------------
static inline void gemm_launch(const float* A, const float* B, float* C,
                               int M, int N, int K, int lda, int ldb, int ldc,
                               const float* bias, int mode)
{
    dim3 grid((N + BN - 1) / BN, (M + BM - 1) / BM);
    sgemm_nt<<<grid, 256>>>(A, B, C, M, N, K, lda, ldb, ldc, bias, mode);
}

extern "C" void kernel_launch(void* const* d_in, const int* in_sizes, int n_in,
                              void* d_out, int out_size)
{
    const float* x = (const float*)d_in[0];
    const float* in_proj[2]  = {(const float*)d_in[1],  (const float*)d_in[10]};
    const float* conv_w[2]   = {(const float*)d_in[2],  (const float*)d_in[11]};
    const float* conv_b[2]   = {(const float*)d_in[3],  (const float*)d_in[12]};
    const float* x_proj[2]   = {(const float*)d_in[4],  (const float*)d_in[13]};
    const float* dt_w[2]     = {(const float*)d_in[5],  (const float*)d_in[14]};
    const float* dt_b[2]     = {(const float*)d_in[6],  (const float*)d_in[15]};
    const float* A_log[2]    = {(const float*)d_in[7],  (const float*)d_in[16]};
    const float* Dp[2]       = {(const float*)d_in[8],  (const float*)d_in[17]};
    const float* out_proj[2] = {(const float*)d_in[9],  (const float*)d_in[18]};
    const float* merge_w     = (const float*)d_in[19];
    float* out = (float*)d_out;

    float *xz0, *xc0, *dbl0, *dl0, *y0, *cat;
    cudaGetSymbolAddress((void**)&xz0, g_xz);
    cudaGetSymbolAddress((void**)&xc0, g_xc);
    cudaGetSymbolAddress((void**)&dbl0, g_dbl);
    cudaGetSymbolAddress((void**)&dl0, g_delta);
    cudaGetSymbolAddress((void**)&y0, g_y);
    cudaGetSymbolAddress((void**)&cat, g_cat);

    for (int d = 0; d < 2; d++) {
        float* xz  = xz0  + (size_t)d * NROWS * 2 * DINNER;
        float* xc  = xc0  + (size_t)d * NROWS * DINNER;
        float* dbl = dbl0 + (size_t)d * NROWS * DBLW;
        float* dlt = dl0  + (size_t)d * NROWS * DINNER;
        float* yb  = y0   + (size_t)d * NROWS * DINNER;

        // in_proj: (2048 x 1024) @ (4096 x 1024)^T -> (2048 x 4096)
        gemm_launch(x, in_proj[d], xz, NROWS, 2 * DINNER, DMODEL,
                    DMODEL, DMODEL, 2 * DINNER, nullptr, 0);

        // depthwise conv + silu
        {
            int total = NROWS * DINNER;
            conv_silu_kernel<<<(total + 255) / 256, 256>>>(xz, conv_w[d],
                                                           conv_b[d], xc, d);
        }

        // x_proj: (2048 x 2048) @ (96 x 2048)^T -> (2048 x 96)
        gemm_launch(xc, x_proj[d], dbl, NROWS, DBLW, DINNER,
                    DINNER, DINNER, DBLW, nullptr, 0);

        // delta = softplus(dt @ dt_w^T + dt_b): (2048 x 64) @ (2048 x 64)^T
        gemm_launch(dbl, dt_w[d], dlt, NROWS, DINNER, DTRANK,
                    DBLW, DTRANK, DINNER, dt_b[d], 1);

        // selective scan + skip + gate
        {
            dim3 grid(DINNER / 128, BSZ);
            scan_kernel<<<grid, 128>>>(dlt, xc, dbl, xz, A_log[d], Dp[d], yb, d);
        }

        // out_proj into concat buffer: (2048 x 2048) @ (1024 x 2048)^T
        gemm_launch(yb, out_proj[d], cat + (size_t)d * DMODEL,
                    NROWS, DMODEL, DINNER, DINNER, DINNER, 2 * DMODEL,
                    nullptr, 0);
    }

    // merge: (2048 x 2048) @ (1024 x 2048)^T -> output (2048 x 1024)
    gemm_launch(cat, merge_w, out, NROWS, DMODEL, 2 * DMODEL,
                2 * DMODEL, 2 * DMODEL, DMODEL, nullptr, 0);
}

// round 7
// speedup vs baseline: 2.2739x; 2.2739x over previous
#include <cuda_runtime.h>
#include <cuda_bf16.h>
#include <math.h>
#include <stdint.h>

#define BSZ 2
#define SEQL 1024
#define DMODEL 1024
#define DINNER 2048
#define DSTATE 16
#define DTRANK 64
#define NROWS (BSZ * SEQL)          // 2048 token rows
#define DBLW 96

// ---------------------------------------------------------------------------
// Scratch (device globals; no allocation allowed)
// ---------------------------------------------------------------------------
__device__ __align__(256) float g_xz[(size_t)NROWS * 8192];              // in_proj out, both dirs (xi_f|z_f|xi_b|z_b)
__device__ __align__(256) float g_xc[2][(size_t)NROWS * DINNER];         // conv+silu fp32
__device__ __align__(256) float g_dbl[2][(size_t)NROWS * DBLW];          // x_proj out (dt|B|C)
__device__ __align__(256) float g_delta[2][(size_t)NROWS * DINNER];      // softplus
__device__ __align__(256) __nv_bfloat16 g_x3[(size_t)NROWS * 3072];      // x split (A-type)
__device__ __align__(256) __nv_bfloat16 g_win3[(size_t)8192 * 3072];     // in_proj w split (B-type, both dirs)
__device__ __align__(256) __nv_bfloat16 g_xc3[2][(size_t)NROWS * 6144];  // xc split (A-type)
__device__ __align__(256) __nv_bfloat16 g_wx3[2][(size_t)256 * 6144];    // x_proj w split (pad 96->256, zero tail)
__device__ __align__(256) __nv_bfloat16 g_dt3[2][(size_t)NROWS * 192];   // dt slice split (A-type)
__device__ __align__(256) __nv_bfloat16 g_wdt3[2][(size_t)DINNER * 192]; // dt_w split
__device__ __align__(256) __nv_bfloat16 g_y3[2][(size_t)NROWS * 6144];   // scan out split (A-type)
__device__ __align__(256) __nv_bfloat16 g_wout3[2][(size_t)DMODEL * 6144];
__device__ __align__(256) __nv_bfloat16 g_cat3[(size_t)NROWS * 6144];    // [f|b] split (A-type, S=2048)
__device__ __align__(256) __nv_bfloat16 g_wm3[(size_t)DMODEL * 6144];

// ---------------------------------------------------------------------------
// PTX helpers (baseline PTX only — no tcgen05; harness builds compute_103)
// ---------------------------------------------------------------------------
__device__ __forceinline__ uint32_t smem_u32(const void* p) {
    uint32_t a;
    asm("{ .reg .u64 t; cvta.to.shared.u64 t, %1; cvt.u32.u64 %0, t; }"
        : "=r"(a) : "l"(p));
    return a;
}
__device__ __forceinline__ void cp16(uint32_t s, const void* g) {
    asm volatile("cp.async.cg.shared.global [%0], [%1], 16;" :: "r"(s), "l"(g));
}
__device__ __forceinline__ void cp_commit() {
    asm volatile("cp.async.commit_group;" ::: "memory");
}
__device__ __forceinline__ void ldm_x4(uint32_t* r, uint32_t addr) {
    asm volatile("ldmatrix.sync.aligned.m8n8.x4.shared.b16 {%0,%1,%2,%3}, [%4];"
                 : "=r"(r[0]), "=r"(r[1]), "=r"(r[2]), "=r"(r[3]) : "r"(addr));
}
__device__ __forceinline__ void ldm_x2(uint32_t& b0, uint32_t& b1, uint32_t addr) {
    asm volatile("ldmatrix.sync.aligned.m8n8.x2.shared.b16 {%0,%1}, [%2];"
                 : "=r"(b0), "=r"(b1) : "r"(addr));
}
__device__ __forceinline__ void mma_bf16(float* d, const uint32_t* a,
                                         uint32_t b0, uint32_t b1) {
    asm volatile("mma.sync.aligned.m16n8k16.row.col.f32.bf16.bf16.f32 "
                 "{%0,%1,%2,%3}, {%4,%5,%6,%7}, {%8,%9}, {%0,%1,%2,%3};"
                 : "+f"(d[0]), "+f"(d[1]), "+f"(d[2]), "+f"(d[3])
                 : "r"(a[0]), "r"(a[1]), "r"(a[2]), "r"(a[3]),
                   "r"(b0), "r"(b1));
}

// ---------------------------------------------------------------------------
// Split conversion: fp32 [R x K] (lda) -> bf16 [Rpad x 3K]
// atype=1: [hi|lo|hi]  (activations / A operand)
// atype=0: [hi|hi|lo]  (weights / B operand)
// ---------------------------------------------------------------------------
__global__ void convert_split(const float* __restrict__ src, int lda,
                              __nv_bfloat16* __restrict__ dst,
                              int R, int K, int Rpad, int atype)
{
    int idx = blockIdx.x * blockDim.x + threadIdx.x;
    if (idx >= Rpad * K) return;
    int r = idx / K, k = idx % K;
    float v = (r < R) ? src[(size_t)r * lda + k] : 0.f;
    __nv_bfloat16 hi = __float2bfloat16(v);
    __nv_bfloat16 lo = __float2bfloat16(v - __bfloat162float(hi));
    size_t base = (size_t)r * 3 * K;
    if (atype) { dst[base + k] = hi; dst[base + K + k] = lo; dst[base + 2 * K + k] = hi; }
    else       { dst[base + k] = hi; dst[base + K + k] = hi; dst[base + 2 * K + k] = lo; }
}

// ---------------------------------------------------------------------------
// HMMA GEMM: C[m,n] = sum_k A[m,k]*B[n,k]  (bf16 K-major operands, fp32 accum)
// Tile BM=128 BN=128 BK=32, 256 thr (8 warps, 2x4, warp tile 64x32),
// cp.async double-buffered SMEM with XOR-swizzled 16B chunks.
// mode 0: fp32 store. 1: softplus(acc+bias[n]). 2: split-bf16 A-type store.
// ---------------------------------------------------------------------------
__global__ __launch_bounds__(256, 2) void gemm_mma(
    const __nv_bfloat16* __restrict__ A, const __nv_bfloat16* __restrict__ B,
    float* __restrict__ Cf, __nv_bfloat16* __restrict__ Cb,
    int M, int Nstore, int K,
    size_t aSZ, size_t bSZ, size_t cSZ,
    int ldc, int mode, const float* __restrict__ bias,
    int splitS, int colOff)
{
    __shared__ __align__(256) __nv_bfloat16 sA[2][128 * 32];
    __shared__ __align__(256) __nv_bfloat16 sB[2][128 * 32];

    const int tid = threadIdx.x;
    const int lane = tid & 31;
    const int w = tid >> 5;
    const int wm = (w >> 2) * 64;     // 0 or 64
    const int wn = (w & 3) * 32;      // 0,32,64,96
    const int z = blockIdx.z;
    const int bm = blockIdx.y * 128;
    const int bn = blockIdx.x * 128;

    const __nv_bfloat16* Ag = A + (size_t)z * aSZ + (size_t)bm * K;
    const __nv_bfloat16* Bg = B + (size_t)z * bSZ + (size_t)bn * K;

    const uint32_t sAb = smem_u32(sA);
    const uint32_t sBb = smem_u32(sB);

    const int r0 = tid >> 2;          // 0..63
    const int cc0 = tid & 3;          // 16B chunk within 64B row

    float acc[4][4][4];
#pragma unroll
    for (int i = 0; i < 4; i++)
#pragma unroll
        for (int j = 0; j < 4; j++)
#pragma unroll
            for (int q = 0; q < 4; q++) acc[i][j][q] = 0.f;

    const int nit = K >> 5;

    // ---- stage loader ----
    auto load_stage = [&](int it, int buf) {
        const size_t kk = (size_t)it * 32;
#pragma unroll
        for (int p = 0; p < 2; ++p) {
            const int r = r0 + p * 64;
            const int sc = cc0 ^ ((r >> 1) & 3);
            cp16(sAb + buf * 8192 + r * 64 + sc * 16,
                 Ag + (size_t)r * K + kk + cc0 * 8);
            cp16(sBb + buf * 8192 + r * 64 + sc * 16,
                 Bg + (size_t)r * K + kk + cc0 * 8);
        }
        cp_commit();
    };

    load_stage(0, 0);

    const int ar = lane & 15;
    const int ac = lane >> 4;             // 0/1 -> +chunk
    const int br = lane & 7;
    const int bc = (lane >> 3) & 1;

    for (int it = 0; it < nit; ++it) {
        const int buf = it & 1;
        if (it + 1 < nit) load_stage(it + 1, buf ^ 1);
        if (it + 1 < nit) asm volatile("cp.async.wait_group 1;" ::: "memory");
        else              asm volatile("cp.async.wait_group 0;" ::: "memory");
        __syncthreads();

#pragma unroll
        for (int ks = 0; ks < 2; ++ks) {
            uint32_t af[4][4];
            const int ach = 2 * ks + ac;
#pragma unroll
            for (int mi = 0; mi < 4; ++mi) {
                const int r = wm + mi * 16 + ar;
                ldm_x4(af[mi], sAb + buf * 8192 + r * 64
                               + ((ach ^ ((r >> 1) & 3)) * 16));
            }
#pragma unroll
            for (int ni = 0; ni < 4; ++ni) {
                const int rn = wn + ni * 8 + br;
                const int bch = 2 * ks + bc;
                uint32_t b0, b1;
                ldm_x2(b0, b1, sBb + buf * 8192 + rn * 64
                               + ((bch ^ ((rn >> 1) & 3)) * 16));
#pragma unroll
                for (int mi = 0; mi < 4; ++mi)
                    mma_bf16(acc[mi][ni], af[mi], b0, b1);
            }
        }
        __syncthreads();
    }

    // ---- epilogue ----
    const int gid = lane >> 2;
    const int tig = lane & 3;
#pragma unroll
    for (int mi = 0; mi < 4; ++mi) {
#pragma unroll
        for (int half = 0; half < 2; ++half) {
            const int m = bm + wm + mi * 16 + gid + half * 8;
#pragma unroll
            for (int ni = 0; ni < 4; ++ni) {
                const int n = bn + wn + ni * 8 + 2 * tig;
                float v0 = acc[mi][ni][half * 2 + 0];
                float v1 = acc[mi][ni][half * 2 + 1];
                if (mode == 2) {
                    size_t base = (size_t)m * (3 * (size_t)splitS) + colOff + n;
                    __nv_bfloat16 h0 = __float2bfloat16(v0);
                    __nv_bfloat16 l0 = __float2bfloat16(v0 - __bfloat162float(h0));
                    __nv_bfloat16 h1 = __float2bfloat16(v1);
                    __nv_bfloat16 l1 = __float2bfloat16(v1 - __bfloat162float(h1));
                    Cb[base] = h0;  Cb[base + 1] = h1;
                    Cb[base + splitS] = l0;  Cb[base + splitS + 1] = l1;
                    Cb[base + 2 * (size_t)splitS] = h0;
                    Cb[base + 2 * (size_t)splitS + 1] = h1;
                } else {
                    if (mode == 1) {
                        v0 += bias[n];
                        v1 += bias[n + 1];
                        v0 = (v0 > 20.f) ? v0 : log1pf(expf(v0));
                        v1 = (v1 > 20.f) ? v1 : log1pf(expf(v1));
                    }
                    if (n + 1 < Nstore) {
                        *(float2*)&Cf[(size_t)z * cSZ + (size_t)m * ldc + n] =
                            make_float2(v0, v1);
                    } else if (n < Nstore) {
                        Cf[(size_t)z * cSZ + (size_t)m * ldc + n] = v0;
                    }
                }
            }
        }
    }
}

// ---------------------------------------------------------------------------
// Depthwise causal conv (d_conv=4) + SiLU; writes fp32 xc AND split-bf16 xc3.
// grid.y = direction (0=causal fwd, 1=anti-causal bwd)
// ---------------------------------------------------------------------------
__global__ void conv_silu_split(const float* __restrict__ xz,
    const float* __restrict__ w0, const float* __restrict__ b0,
    const float* __restrict__ w1, const float* __restrict__ b1,
    float* __restrict__ xc0, float* __restrict__ xc1,
    __nv_bfloat16* __restrict__ q0, __nv_bfloat16* __restrict__ q1)
{
    int idx = blockIdx.x * blockDim.x + threadIdx.x;
    if (idx >= NROWS * DINNER) return;
    const int d = blockIdx.y;
    const int e = idx % DINNER;
    const int row = idx / DINNER;
    const int l = row % SEQL;
    const int b = row / SEQL;

    const float* w = d ? w1 : w0;
    float acc = d ? b1[e] : b0[e];
    #pragma unroll
    for (int k = 0; k < 4; ++k) {
        int li = d ? (l + 3 - k) : (l - 3 + k);
        if (li >= 0 && li < SEQL)
            acc = fmaf(w[e * 4 + k],
                       xz[(size_t)(b * SEQL + li) * 8192 + d * 4096 + e], acc);
    }
    float s = acc / (1.f + expf(-acc));
    float* xc = d ? xc1 : xc0;
    __nv_bfloat16* q = d ? q1 : q0;
    xc[(size_t)row * DINNER + e] = s;
    __nv_bfloat16 hi = __float2bfloat16(s);
    __nv_bfloat16 lo = __float2bfloat16(s - __bfloat162float(hi));
    size_t base = (size_t)row * 6144 + e;
    q[base] = hi; q[base + 2048] = lo; q[base + 4096] = hi;
}

// ---------------------------------------------------------------------------
// Selective scan + skip + gate; both directions (grid.z). Writes split-bf16 y3.
// ---------------------------------------------------------------------------
__global__ __launch_bounds__(128) void scan_kernel(
    const float* __restrict__ dl0, const float* __restrict__ dl1,
    const float* __restrict__ xc0, const float* __restrict__ xc1,
    const float* __restrict__ db0, const float* __restrict__ db1,
    const float* __restrict__ xz,
    const float* __restrict__ Al0, const float* __restrict__ Al1,
    const float* __restrict__ Dp0, const float* __restrict__ Dp1,
    __nv_bfloat16* __restrict__ y30, __nv_bfloat16* __restrict__ y31)
{
    const int e = blockIdx.x * 128 + threadIdx.x;
    const int b = blockIdx.y;
    const int d = blockIdx.z;
    const float* delta = d ? dl1 : dl0;
    const float* xc    = d ? xc1 : xc0;
    const float* dbl   = d ? db1 : db0;
    const float* A_log = d ? Al1 : Al0;
    const float* Dp    = d ? Dp1 : Dp0;
    __nv_bfloat16* y3  = d ? y31 : y30;

    float Av[DSTATE];
    #pragma unroll
    for (int n = 0; n < DSTATE; n++) Av[n] = -expf(A_log[e * DSTATE + n]);

    bool structured = true;
    #pragma unroll
    for (int n = 0; n < DSTATE; n++)
        structured = structured &&
            (fabsf(Av[n] - (float)(n + 1) * Av[0]) <= 1e-5f * fabsf(Av[n]) + 1e-7f);
    structured = __all_sync(0xffffffffu, structured);

    const float Dd = Dp[e];
    float h[DSTATE];
    #pragma unroll
    for (int n = 0; n < DSTATE; n++) h[n] = 0.f;

    for (int t = 0; t < SEQL; t++) {
        const int l = d ? (SEQL - 1 - t) : t;
        const size_t row = (size_t)b * SEQL + l;

        const float dlt = delta[row * DINNER + e];
        const float xcv = xc[row * DINNER + e];
        const float zz  = xz[row * 8192 + d * 4096 + 2048 + e];

        const float4* bcp = (const float4*)(dbl + row * DBLW + DTRANK);
        float4 B0 = bcp[0], B1 = bcp[1], B2 = bcp[2], B3 = bcp[3];
        float4 C0 = bcp[4], C1 = bcp[5], C2 = bcp[6], C3 = bcp[7];
        float Bv[16] = {B0.x, B0.y, B0.z, B0.w, B1.x, B1.y, B1.z, B1.w,
                        B2.x, B2.y, B2.z, B2.w, B3.x, B3.y, B3.z, B3.w};
        float Cv[16] = {C0.x, C0.y, C0.z, C0.w, C1.x, C1.y, C1.z, C1.w,
                        C2.x, C2.y, C2.z, C2.w, C3.x, C3.y, C3.z, C3.w};

        const float du = dlt * xcv;
        float yacc = 0.f;

        if (structured) {
            const float e1 = __expf(dlt * Av[0]);
            float p = e1;
            #pragma unroll
            for (int n = 0; n < DSTATE; n++) {
                h[n] = fmaf(p, h[n], du * Bv[n]);
                yacc = fmaf(h[n], Cv[n], yacc);
                p *= e1;
            }
        } else {
            #pragma unroll
            for (int n = 0; n < DSTATE; n++) {
                float dA = __expf(dlt * Av[n]);
                h[n] = fmaf(dA, h[n], du * Bv[n]);
                yacc = fmaf(h[n], Cv[n], yacc);
            }
        }

        float yv = fmaf(xcv, Dd, yacc);
        float sz = zz / (1.f + __expf(-zz));
        float out = yv * sz;
        __nv_bfloat16 hi = __float2bfloat16(out);
        __nv_bfloat16 lo = __float2bfloat16(out - __bfloat162float(hi));
        size_t base = row * 6144 + e;
        y3[base] = hi; y3[base + 2048] = lo; y3[base + 4096] = hi;
    }
}

// ---------------------------------------------------------------------------
// Host launch
// ---------------------------------------------------------------------------
static inline void tc_gemm(const __nv_bfloat16* A, const __nv_bfloat16* B,
                           float* Cf, __nv_bfloat16* Cb,
                           int M, int Nstore, int Npad, int K,
                           size_t aSZ, size_t bSZ, size_t cSZ,
                           int ldc, int mode, const float* bias,
                           int splitS, int colOff, int Z)
{
    dim3 grid(Npad / 128, M / 128, Z);
    gemm_mma<<<grid, 256>>>(A, B, Cf, Cb, M, Nstore, K,
                            aSZ, bSZ, cSZ, ldc, mode, bias, splitS, colOff);
}

static inline void conv_launch(const float* src, int lda, __nv_bfloat16* dst,
                               int R, int K, int Rpad, int atype)
{
    int total = Rpad * K;
    convert_split<<<(total + 255) / 256, 256>>>(src, lda, dst, R, K, Rpad, atype);
}

extern "C" void kernel_launch(void* const* d_in, const int* in_sizes, int n_in,
                              void* d_out, int out_size)
{
    const float* x = (const float*)d_in[0];
    const float* in_proj[2]  = {(const float*)d_in[1],  (const float*)d_in[10]};
    const float* conv_w[2]   = {(const float*)d_in[2],  (const float*)d_in[11]};
    const float* conv_b[2]   = {(const float*)d_in[3],  (const float*)d_in[12]};
    const float* x_proj[2]   = {(const float*)d_in[4],  (const float*)d_in[13]};
    const float* dt_w[2]     = {(const float*)d_in[5],  (const float*)d_in[14]};
    const float* dt_b[2]     = {(const float*)d_in[6],  (const float*)d_in[15]};
    const float* A_log[2]    = {(const float*)d_in[7],  (const float*)d_in[16]};
    const float* Dp[2]       = {(const float*)d_in[8],  (const float*)d_in[17]};
    const float* out_proj[2] = {(const float*)d_in[9],  (const float*)d_in[18]};
    const float* merge_w     = (const float*)d_in[19];
    float* out = (float*)d_out;

    float *xz, *xc, *dbl, *dlt;
    __nv_bfloat16 *x3, *win3, *xc3, *wx3, *dt3, *wdt3, *y3, *wout3, *cat3, *wm3;
    cudaGetSymbolAddress((void**)&xz, g_xz);
    cudaGetSymbolAddress((void**)&xc, g_xc);
    cudaGetSymbolAddress((void**)&dbl, g_dbl);
    cudaGetSymbolAddress((void**)&dlt, g_delta);
    cudaGetSymbolAddress((void**)&x3, g_x3);
    cudaGetSymbolAddress((void**)&win3, g_win3);
    cudaGetSymbolAddress((void**)&xc3, g_xc3);
    cudaGetSymbolAddress((void**)&wx3, g_wx3);
    cudaGetSymbolAddress((void**)&dt3, g_dt3);
    cudaGetSymbolAddress((void**)&wdt3, g_wdt3);
    cudaGetSymbolAddress((void**)&y3, g_y3);
    cudaGetSymbolAddress((void**)&wout3, g_wout3);
    cudaGetSymbolAddress((void**)&cat3, g_cat3);
    cudaGetSymbolAddress((void**)&wm3, g_wm3);

    const size_t XC = (size_t)NROWS * DINNER;
    const size_t XC3 = (size_t)NROWS * 6144;
    const size_t DBLSZ = (size_t)NROWS * DBLW;
    const size_t DT3 = (size_t)NROWS * 192;

    // ---- operand conversions (fp32 -> split bf16) ----
    conv_launch(x, DMODEL, x3, NROWS, DMODEL, NROWS, 1);
    conv_launch(in_proj[0], DMODEL, win3, 4096, DMODEL, 4096, 0);
    conv_launch(in_proj[1], DMODEL, win3 + (size_t)4096 * 3072, 4096, DMODEL, 4096, 0);
    for (int d = 0; d < 2; d++) {
        conv_launch(x_proj[d], DINNER, wx3 + (size_t)d * 256 * 6144, DBLW, DINNER, 256, 0);
        conv_launch(dt_w[d], DTRANK, wdt3 + (size_t)d * DINNER * 192, DINNER, DTRANK, DINNER, 0);
        conv_launch(out_proj[d], DINNER, wout3 + (size_t)d * DMODEL * 6144, DMODEL, DINNER, DMODEL, 0);
    }
    conv_launch(merge_w, 2 * DMODEL, wm3, DMODEL, 2 * DMODEL, DMODEL, 0);

    // ---- in_proj both dirs: (2048 x 8192) = x3 @ win3^T ----
    tc_gemm(x3, win3, xz, nullptr, NROWS, 8192, 8192, 3072,
            0, 0, 0, 8192, 0, nullptr, 0, 0, 1);

    // ---- conv + silu + split, both dirs ----
    {
        dim3 grid((NROWS * DINNER + 255) / 256, 2);
        conv_silu_split<<<grid, 256>>>(xz, conv_w[0], conv_b[0], conv_w[1], conv_b[1],
                                       xc, xc + XC, xc3, xc3 + XC3);
    }

    // ---- x_proj both dirs (z-batched): (2048 x 96) = xc3 @ wx3^T ----
    tc_gemm(xc3, wx3, dbl, nullptr, NROWS, DBLW, 128, 6144,
            XC3, (size_t)256 * 6144, DBLSZ, DBLW, 0, nullptr, 0, 0, 2);

    // ---- dt slice conversion + dt GEMM (softplus epilogue) per dir ----
    for (int d = 0; d < 2; d++) {
        conv_launch(dbl + d * DBLSZ, DBLW, dt3 + d * DT3, NROWS, DTRANK, NROWS, 1);
        tc_gemm(dt3 + d * DT3, wdt3 + (size_t)d * DINNER * 192,
                dlt + d * XC, nullptr, NROWS, DINNER, DINNER, 192,
                0, 0, 0, DINNER, 1, dt_b[d], 0, 0, 1);
    }

    // ---- selective scan both dirs, writes split y3 ----
    {
        dim3 grid(DINNER / 128, BSZ, 2);
        scan_kernel<<<grid, 128>>>(dlt, dlt + XC, xc, xc + XC, dbl, dbl + DBLSZ,
                                   xz, A_log[0], A_log[1], Dp[0], Dp[1],
                                   y3, y3 + XC3);
    }

    // ---- out_proj per dir -> split-bf16 concat buffer ----
    for (int d = 0; d < 2; d++) {
        tc_gemm(y3 + d * XC3, wout3 + (size_t)d * DMODEL * 6144,
                nullptr, cat3, NROWS, DMODEL, DMODEL, 6144,
                0, 0, 0, 0, 2, nullptr, 2 * DMODEL, d * DMODEL, 1);
    }

    // ---- merge: (2048 x 1024) = cat3 @ wm3^T -> output ----
    tc_gemm(cat3, wm3, out, nullptr, NROWS, DMODEL, DMODEL, 6144,
            0, 0, 0, DMODEL, 0, nullptr, 0, 0, 1);
}

// round 8
// speedup vs baseline: 2.3295x; 1.0245x over previous
#include <cuda_runtime.h>
#include <cuda_bf16.h>
#include <math.h>
#include <stdint.h>

#define BSZ 2
#define SEQL 1024
#define DMODEL 1024
#define DINNER 2048
#define DSTATE 16
#define DTRANK 64
#define NROWS (BSZ * SEQL)          // 2048 token rows
#define DBLW 96

// ---------------------------------------------------------------------------
// Scratch (device globals; no allocation allowed)
// ---------------------------------------------------------------------------
__device__ __align__(256) float g_xz[(size_t)NROWS * 8192];              // in_proj out, both dirs
__device__ __align__(256) float g_xc[2][(size_t)NROWS * DINNER];         // conv+silu fp32
__device__ __align__(256) float g_dbl[2][(size_t)NROWS * DBLW];          // x_proj out (dt|B|C)
__device__ __align__(256) float g_delta[2][(size_t)NROWS * DINNER];      // softplus
__device__ __align__(256) __nv_bfloat16 g_x3[(size_t)NROWS * 3072];      // x split (A-type)
__device__ __align__(256) __nv_bfloat16 g_win3[(size_t)8192 * 3072];     // in_proj w split (both dirs)
__device__ __align__(256) __nv_bfloat16 g_xc3[2][(size_t)NROWS * 6144];  // xc split (A-type)
__device__ __align__(256) __nv_bfloat16 g_wx3[2][(size_t)256 * 6144];    // x_proj w split (pad 96->256)
__device__ __align__(256) __nv_bfloat16 g_dt3[2][(size_t)NROWS * 192];   // dt slice split (A-type)
__device__ __align__(256) __nv_bfloat16 g_wdt3[2][(size_t)DINNER * 192]; // dt_w split
__device__ __align__(256) __nv_bfloat16 g_y3[2][(size_t)NROWS * 6144];   // scan out split (A-type)
__device__ __align__(256) __nv_bfloat16 g_wout3[2][(size_t)DMODEL * 6144];
__device__ __align__(256) __nv_bfloat16 g_cat3[(size_t)NROWS * 6144];    // [f|b] split (A-type)
__device__ __align__(256) __nv_bfloat16 g_wm3[(size_t)DMODEL * 6144];

// ---------------------------------------------------------------------------
// PTX helpers (baseline PTX only — compute_103)
// ---------------------------------------------------------------------------
__device__ __forceinline__ uint32_t smem_u32(const void* p) {
    uint32_t a;
    asm("{ .reg .u64 t; cvta.to.shared.u64 t, %1; cvt.u32.u64 %0, t; }"
        : "=r"(a) : "l"(p));
    return a;
}
__device__ __forceinline__ void cp16(uint32_t s, const void* g) {
    asm volatile("cp.async.cg.shared.global [%0], [%1], 16;" :: "r"(s), "l"(g));
}
__device__ __forceinline__ void cp_commit() {
    asm volatile("cp.async.commit_group;" ::: "memory");
}
__device__ __forceinline__ void ldm_x4(uint32_t* r, uint32_t addr) {
    asm volatile("ldmatrix.sync.aligned.m8n8.x4.shared.b16 {%0,%1,%2,%3}, [%4];"
                 : "=r"(r[0]), "=r"(r[1]), "=r"(r[2]), "=r"(r[3]) : "r"(addr));
}
__device__ __forceinline__ void ldm_x2(uint32_t& b0, uint32_t& b1, uint32_t addr) {
    asm volatile("ldmatrix.sync.aligned.m8n8.x2.shared.b16 {%0,%1}, [%2];"
                 : "=r"(b0), "=r"(b1) : "r"(addr));
}
__device__ __forceinline__ void mma_bf16(float* d, const uint32_t* a,
                                         uint32_t b0, uint32_t b1) {
    asm volatile("mma.sync.aligned.m16n8k16.row.col.f32.bf16.bf16.f32 "
                 "{%0,%1,%2,%3}, {%4,%5,%6,%7}, {%8,%9}, {%0,%1,%2,%3};"
                 : "+f"(d[0]), "+f"(d[1]), "+f"(d[2]), "+f"(d[3])
                 : "r"(a[0]), "r"(a[1]), "r"(a[2]), "r"(a[3]),
                   "r"(b0), "r"(b1));
}

// ---------------------------------------------------------------------------
// Split conversion: fp32 [R x K] (lda) -> bf16 [Rpad x 3K]
// atype=1: [hi|lo|hi]  (A operand)   atype=0: [hi|hi|lo]  (B operand)
// ---------------------------------------------------------------------------
__global__ void convert_split(const float* __restrict__ src, int lda,
                              __nv_bfloat16* __restrict__ dst,
                              int R, int K, int Rpad, int atype)
{
    int idx = blockIdx.x * blockDim.x + threadIdx.x;
    if (idx >= Rpad * K) return;
    int r = idx / K, k = idx % K;
    float v = (r < R) ? src[(size_t)r * lda + k] : 0.f;
    __nv_bfloat16 hi = __float2bfloat16(v);
    __nv_bfloat16 lo = __float2bfloat16(v - __bfloat162float(hi));
    size_t base = (size_t)r * 3 * K;
    if (atype) { dst[base + k] = hi; dst[base + K + k] = lo; dst[base + 2 * K + k] = hi; }
    else       { dst[base + k] = hi; dst[base + K + k] = hi; dst[base + 2 * K + k] = lo; }
}

// ---------------------------------------------------------------------------
// HMMA GEMM: C[m,n] = sum_k A[m,k]*B[n,k]  (bf16 K-major, fp32 accum)
// BM=128, BN template (128 or 256), BK=32, 256 threads (8 warps 2x4),
// warp tile 64x(BN/4). 3-stage cp.async pipeline, ONE __syncthreads per iter.
// mode 0: fp32 store. 1: softplus(acc+bias_z[n]). 2: split-bf16 A-type store.
// ---------------------------------------------------------------------------
template <int BN>
__global__ __launch_bounds__(256, (BN == 128) ? 2 : 1) void gemm_mma(
    const __nv_bfloat16* __restrict__ A, const __nv_bfloat16* __restrict__ B,
    float* __restrict__ Cf, __nv_bfloat16* __restrict__ Cb,
    int M, int Nstore, int K,
    size_t aSZ, size_t bSZ, size_t cSZ,
    int ldc, int mode,
    const float* __restrict__ bias0, const float* __restrict__ bias1,
    int splitS, int colOff, int colZ)
{
    constexpr int NI = BN / 32;           // n-tiles per warp (4 or 8)
    constexpr int WN = BN / 4;            // warp n extent (32 or 64)
    constexpr int ASTG = 128 * 64;        // A stage bytes
    constexpr int BSTG = BN * 64;         // B stage bytes

    extern __shared__ char dynsmem[];
    const uint32_t sAb = smem_u32(dynsmem);
    const uint32_t sBb = sAb + 3 * ASTG;

    const int tid = threadIdx.x;
    const int lane = tid & 31;
    const int w = tid >> 5;
    const int wm = (w >> 2) * 64;
    const int wn = (w & 3) * WN;
    const int z = blockIdx.z;
    const int bm = blockIdx.y * 128;
    const int bn = blockIdx.x * BN;

    const __nv_bfloat16* Ag = A + (size_t)z * aSZ + (size_t)bm * K;
    const __nv_bfloat16* Bg = B + (size_t)z * bSZ + (size_t)bn * K;

    const int r0 = tid >> 2;              // 0..63
    const int cc0 = tid & 3;              // 16B chunk in 64B row

    float acc[4][NI][4];
#pragma unroll
    for (int i = 0; i < 4; i++)
#pragma unroll
        for (int j = 0; j < NI; j++)
#pragma unroll
            for (int q = 0; q < 4; q++) acc[i][j][q] = 0.f;

    const int nit = K >> 5;

    auto load_stage = [&](int it, int s) {
        const size_t kk = (size_t)it * 32;
#pragma unroll
        for (int p = 0; p < 2; ++p) {
            const int r = r0 + p * 64;
            const int sc = cc0 ^ ((r >> 1) & 3);
            cp16(sAb + s * ASTG + r * 64 + sc * 16,
                 Ag + (size_t)r * K + kk + cc0 * 8);
        }
#pragma unroll
        for (int p = 0; p < BN / 64; ++p) {
            const int r = r0 + p * 64;
            const int sc = cc0 ^ ((r >> 1) & 3);
            cp16(sBb + s * BSTG + r * 64 + sc * 16,
                 Bg + (size_t)r * K + kk + cc0 * 8);
        }
        cp_commit();
    };

    load_stage(0, 0);
    load_stage(1, 1);

    const int ar = lane & 15;
    const int ac = lane >> 4;
    const int br = lane & 7;
    const int bc = (lane >> 3) & 1;

    int s = 0;
    for (int it = 0; it < nit; ++it) {
        if (it + 1 < nit) asm volatile("cp.async.wait_group 1;" ::: "memory");
        else              asm volatile("cp.async.wait_group 0;" ::: "memory");
        __syncthreads();
        if (it + 2 < nit) {
            int s2 = s + 2; if (s2 >= 3) s2 -= 3;
            load_stage(it + 2, s2);
        }

#pragma unroll
        for (int ks = 0; ks < 2; ++ks) {
            uint32_t af[4][4];
            const int ach = 2 * ks + ac;
#pragma unroll
            for (int mi = 0; mi < 4; ++mi) {
                const int r = wm + mi * 16 + ar;
                ldm_x4(af[mi], sAb + s * ASTG + r * 64
                               + ((ach ^ ((r >> 1) & 3)) * 16));
            }
            const int bch = 2 * ks + bc;
#pragma unroll
            for (int ni = 0; ni < NI; ++ni) {
                const int rn = wn + ni * 8 + br;
                uint32_t b0, b1;
                ldm_x2(b0, b1, sBb + s * BSTG + rn * 64
                               + ((bch ^ ((rn >> 1) & 3)) * 16));
#pragma unroll
                for (int mi = 0; mi < 4; ++mi)
                    mma_bf16(acc[mi][ni], af[mi], b0, b1);
            }
        }
        if (++s >= 3) s -= 3;
    }

    // ---- epilogue ----
    const float* bias = z ? bias1 : bias0;
    const int co = colOff + z * colZ;
    const int gid = lane >> 2;
    const int tig = lane & 3;
#pragma unroll
    for (int mi = 0; mi < 4; ++mi) {
#pragma unroll
        for (int half = 0; half < 2; ++half) {
            const int m = bm + wm + mi * 16 + gid + half * 8;
#pragma unroll
            for (int ni = 0; ni < NI; ++ni) {
                const int n = bn + wn + ni * 8 + 2 * tig;
                float v0 = acc[mi][ni][half * 2 + 0];
                float v1 = acc[mi][ni][half * 2 + 1];
                if (mode == 2) {
                    size_t base = (size_t)m * (3 * (size_t)splitS) + co + n;
                    __nv_bfloat16 h0 = __float2bfloat16(v0);
                    __nv_bfloat16 l0 = __float2bfloat16(v0 - __bfloat162float(h0));
                    __nv_bfloat16 h1 = __float2bfloat16(v1);
                    __nv_bfloat16 l1 = __float2bfloat16(v1 - __bfloat162float(h1));
                    Cb[base] = h0;  Cb[base + 1] = h1;
                    Cb[base + splitS] = l0;  Cb[base + splitS + 1] = l1;
                    Cb[base + 2 * (size_t)splitS] = h0;
                    Cb[base + 2 * (size_t)splitS + 1] = h1;
                } else {
                    if (mode == 1) {
                        v0 += bias[n];
                        v1 += bias[n + 1];
                        v0 = (v0 > 20.f) ? v0 : log1pf(expf(v0));
                        v1 = (v1 > 20.f) ? v1 : log1pf(expf(v1));
                    }
                    if (n + 1 < Nstore) {
                        *(float2*)&Cf[(size_t)z * cSZ + (size_t)m * ldc + n] =
                            make_float2(v0, v1);
                    } else if (n < Nstore) {
                        Cf[(size_t)z * cSZ + (size_t)m * ldc + n] = v0;
                    }
                }
            }
        }
    }
}

// ---------------------------------------------------------------------------
// Depthwise causal conv (d_conv=4) + SiLU; writes fp32 xc AND split-bf16 xc3.
// ---------------------------------------------------------------------------
__global__ void conv_silu_split(const float* __restrict__ xz,
    const float* __restrict__ w0, const float* __restrict__ b0,
    const float* __restrict__ w1, const float* __restrict__ b1,
    float* __restrict__ xc0, float* __restrict__ xc1,
    __nv_bfloat16* __restrict__ q0, __nv_bfloat16* __restrict__ q1)
{
    int idx = blockIdx.x * blockDim.x + threadIdx.x;
    if (idx >= NROWS * DINNER) return;
    const int d = blockIdx.y;
    const int e = idx % DINNER;
    const int row = idx / DINNER;
    const int l = row % SEQL;
    const int b = row / SEQL;

    const float* w = d ? w1 : w0;
    float acc = d ? b1[e] : b0[e];
    #pragma unroll
    for (int k = 0; k < 4; ++k) {
        int li = d ? (l + 3 - k) : (l - 3 + k);
        if (li >= 0 && li < SEQL)
            acc = fmaf(w[e * 4 + k],
                       xz[(size_t)(b * SEQL + li) * 8192 + d * 4096 + e], acc);
    }
    float s = acc / (1.f + expf(-acc));
    float* xc = d ? xc1 : xc0;
    __nv_bfloat16* q = d ? q1 : q0;
    xc[(size_t)row * DINNER + e] = s;
    __nv_bfloat16 hi = __float2bfloat16(s);
    __nv_bfloat16 lo = __float2bfloat16(s - __bfloat162float(hi));
    size_t base = (size_t)row * 6144 + e;
    q[base] = hi; q[base + 2048] = lo; q[base + 4096] = hi;
}

// ---------------------------------------------------------------------------
// Selective scan + skip + gate; both directions. 64-thread blocks for spread.
// ---------------------------------------------------------------------------
__global__ __launch_bounds__(64) void scan_kernel(
    const float* __restrict__ dl0, const float* __restrict__ dl1,
    const float* __restrict__ xc0, const float* __restrict__ xc1,
    const float* __restrict__ db0, const float* __restrict__ db1,
    const float* __restrict__ xz,
    const float* __restrict__ Al0, const float* __restrict__ Al1,
    const float* __restrict__ Dp0, const float* __restrict__ Dp1,
    __nv_bfloat16* __restrict__ y30, __nv_bfloat16* __restrict__ y31)
{
    const int e = blockIdx.x * 64 + threadIdx.x;
    const int b = blockIdx.y;
    const int d = blockIdx.z;
    const float* delta = d ? dl1 : dl0;
    const float* xc    = d ? xc1 : xc0;
    const float* dbl   = d ? db1 : db0;
    const float* A_log = d ? Al1 : Al0;
    const float* Dp    = d ? Dp1 : Dp0;
    __nv_bfloat16* y3  = d ? y31 : y30;

    float Av[DSTATE];
    #pragma unroll
    for (int n = 0; n < DSTATE; n++) Av[n] = -expf(A_log[e * DSTATE + n]);

    bool structured = true;
    #pragma unroll
    for (int n = 0; n < DSTATE; n++)
        structured = structured &&
            (fabsf(Av[n] - (float)(n + 1) * Av[0]) <= 1e-5f * fabsf(Av[n]) + 1e-7f);
    structured = __all_sync(0xffffffffu, structured);

    const float Dd = Dp[e];
    float h[DSTATE];
    #pragma unroll
    for (int n = 0; n < DSTATE; n++) h[n] = 0.f;

    for (int t = 0; t < SEQL; t++) {
        const int l = d ? (SEQL - 1 - t) : t;
        const size_t row = (size_t)b * SEQL + l;

        const float dlt = delta[row * DINNER + e];
        const float xcv = xc[row * DINNER + e];
        const float zz  = xz[row * 8192 + d * 4096 + 2048 + e];

        const float4* bcp = (const float4*)(dbl + row * DBLW + DTRANK);
        float4 B0 = bcp[0], B1 = bcp[1], B2 = bcp[2], B3 = bcp[3];
        float4 C0 = bcp[4], C1 = bcp[5], C2 = bcp[6], C3 = bcp[7];
        float Bv[16] = {B0.x, B0.y, B0.z, B0.w, B1.x, B1.y, B1.z, B1.w,
                        B2.x, B2.y, B2.z, B2.w, B3.x, B3.y, B3.z, B3.w};
        float Cv[16] = {C0.x, C0.y, C0.z, C0.w, C1.x, C1.y, C1.z, C1.w,
                        C2.x, C2.y, C2.z, C2.w, C3.x, C3.y, C3.z, C3.w};

        const float du = dlt * xcv;
        float yacc = 0.f;

        if (structured) {
            const float e1 = __expf(dlt * Av[0]);
            float p = e1;
            #pragma unroll
            for (int n = 0; n < DSTATE; n++) {
                h[n] = fmaf(p, h[n], du * Bv[n]);
                yacc = fmaf(h[n], Cv[n], yacc);
                p *= e1;
            }
        } else {
            #pragma unroll
            for (int n = 0; n < DSTATE; n++) {
                float dA = __expf(dlt * Av[n]);
                h[n] = fmaf(dA, h[n], du * Bv[n]);
                yacc = fmaf(h[n], Cv[n], yacc);
            }
        }

        float yv = fmaf(xcv, Dd, yacc);
        float sz = zz / (1.f + __expf(-zz));
        float out = yv * sz;
        __nv_bfloat16 hi = __float2bfloat16(out);
        __nv_bfloat16 lo = __float2bfloat16(out - __bfloat162float(hi));
        size_t base = row * 6144 + e;
        y3[base] = hi; y3[base + 2048] = lo; y3[base + 4096] = hi;
    }
}

// ---------------------------------------------------------------------------
// Host launch
// ---------------------------------------------------------------------------
#define SMEM_128 (3 * (128 * 64 + 128 * 64))   // 48 KB
#define SMEM_256 (3 * (128 * 64 + 256 * 64))   // 72 KB

template <int BN>
static inline void tc_gemm(const __nv_bfloat16* A, const __nv_bfloat16* B,
                           float* Cf, __nv_bfloat16* Cb,
                           int M, int Nstore, int Npad, int K,
                           size_t aSZ, size_t bSZ, size_t cSZ,
                           int ldc, int mode,
                           const float* bias0, const float* bias1,
                           int splitS, int colOff, int colZ, int Z)
{
    dim3 grid(Npad / BN, M / 128, Z);
    int smem = (BN == 128) ? SMEM_128 : SMEM_256;
    gemm_mma<BN><<<grid, 256, smem>>>(A, B, Cf, Cb, M, Nstore, K,
                                      aSZ, bSZ, cSZ, ldc, mode,
                                      bias0, bias1, splitS, colOff, colZ);
}

static inline void conv_launch(const float* src, int lda, __nv_bfloat16* dst,
                               int R, int K, int Rpad, int atype)
{
    int total = Rpad * K;
    convert_split<<<(total + 255) / 256, 256>>>(src, lda, dst, R, K, Rpad, atype);
}

extern "C" void kernel_launch(void* const* d_in, const int* in_sizes, int n_in,
                              void* d_out, int out_size)
{
    const float* x = (const float*)d_in[0];
    const float* in_proj[2]  = {(const float*)d_in[1],  (const float*)d_in[10]};
    const float* conv_w[2]   = {(const float*)d_in[2],  (const float*)d_in[11]};
    const float* conv_b[2]   = {(const float*)d_in[3],  (const float*)d_in[12]};
    const float* x_proj[2]   = {(const float*)d_in[4],  (const float*)d_in[13]};
    const float* dt_w[2]     = {(const float*)d_in[5],  (const float*)d_in[14]};
    const float* dt_b[2]     = {(const float*)d_in[6],  (const float*)d_in[15]};
    const float* A_log[2]    = {(const float*)d_in[7],  (const float*)d_in[16]};
    const float* Dp[2]       = {(const float*)d_in[8],  (const float*)d_in[17]};
    const float* out_proj[2] = {(const float*)d_in[9],  (const float*)d_in[18]};
    const float* merge_w     = (const float*)d_in[19];
    float* out = (float*)d_out;

    cudaFuncSetAttribute(gemm_mma<128>,
                         cudaFuncAttributeMaxDynamicSharedMemorySize, SMEM_128);
    cudaFuncSetAttribute(gemm_mma<256>,
                         cudaFuncAttributeMaxDynamicSharedMemorySize, SMEM_256);

    float *xz, *xc, *dbl, *dlt;
    __nv_bfloat16 *x3, *win3, *xc3, *wx3, *dt3, *wdt3, *y3, *wout3, *cat3, *wm3;
    cudaGetSymbolAddress((void**)&xz, g_xz);
    cudaGetSymbolAddress((void**)&xc, g_xc);
    cudaGetSymbolAddress((void**)&dbl, g_dbl);
    cudaGetSymbolAddress((void**)&dlt, g_delta);
    cudaGetSymbolAddress((void**)&x3, g_x3);
    cudaGetSymbolAddress((void**)&win3, g_win3);
    cudaGetSymbolAddress((void**)&xc3, g_xc3);
    cudaGetSymbolAddress((void**)&wx3, g_wx3);
    cudaGetSymbolAddress((void**)&dt3, g_dt3);
    cudaGetSymbolAddress((void**)&wdt3, g_wdt3);
    cudaGetSymbolAddress((void**)&y3, g_y3);
    cudaGetSymbolAddress((void**)&wout3, g_wout3);
    cudaGetSymbolAddress((void**)&cat3, g_cat3);
    cudaGetSymbolAddress((void**)&wm3, g_wm3);

    const size_t XC = (size_t)NROWS * DINNER;
    const size_t XC3 = (size_t)NROWS * 6144;
    const size_t DBLSZ = (size_t)NROWS * DBLW;
    const size_t DT3 = (size_t)NROWS * 192;

    // ---- operand conversions (fp32 -> split bf16) ----
    conv_launch(x, DMODEL, x3, NROWS, DMODEL, NROWS, 1);
    conv_launch(in_proj[0], DMODEL, win3, 4096, DMODEL, 4096, 0);
    conv_launch(in_proj[1], DMODEL, win3 + (size_t)4096 * 3072, 4096, DMODEL, 4096, 0);
    for (int d = 0; d < 2; d++) {
        conv_launch(x_proj[d], DINNER, wx3 + (size_t)d * 256 * 6144, DBLW, DINNER, 256, 0);
        conv_launch(dt_w[d], DTRANK, wdt3 + (size_t)d * DINNER * 192, DINNER, DTRANK, DINNER, 0);
        conv_launch(out_proj[d], DINNER, wout3 + (size_t)d * DMODEL * 6144, DMODEL, DINNER, DMODEL, 0);
    }
    conv_launch(merge_w, 2 * DMODEL, wm3, DMODEL, 2 * DMODEL, DMODEL, 0);

    // ---- in_proj both dirs: (2048 x 8192) = x3 @ win3^T  (big tiles) ----
    tc_gemm<256>(x3, win3, xz, nullptr, NROWS, 8192, 8192, 3072,
                 0, 0, 0, 8192, 0, nullptr, nullptr, 0, 0, 0, 1);

    // ---- conv + silu + split, both dirs ----
    {
        dim3 grid((NROWS * DINNER + 255) / 256, 2);
        conv_silu_split<<<grid, 256>>>(xz, conv_w[0], conv_b[0], conv_w[1], conv_b[1],
                                       xc, xc + XC, xc3, xc3 + XC3);
    }

    // ---- x_proj both dirs (z-batched): (2048 x 96) = xc3 @ wx3^T ----
    tc_gemm<128>(xc3, wx3, dbl, nullptr, NROWS, DBLW, 128, 6144,
                 XC3, (size_t)256 * 6144, DBLSZ, DBLW, 0, nullptr, nullptr,
                 0, 0, 0, 2);

    // ---- dt slice conversion + z-batched dt GEMM (softplus epilogue) ----
    for (int d = 0; d < 2; d++)
        conv_launch(dbl + d * DBLSZ, DBLW, dt3 + d * DT3, NROWS, DTRANK, NROWS, 1);
    tc_gemm<128>(dt3, wdt3, dlt, nullptr, NROWS, DINNER, DINNER, 192,
                 DT3, (size_t)DINNER * 192, XC, DINNER, 1, dt_b[0], dt_b[1],
                 0, 0, 0, 2);

    // ---- selective scan both dirs, writes split y3 ----
    {
        dim3 grid(DINNER / 64, BSZ, 2);
        scan_kernel<<<grid, 64>>>(dlt, dlt + XC, xc, xc + XC, dbl, dbl + DBLSZ,
                                  xz, A_log[0], A_log[1], Dp[0], Dp[1],
                                  y3, y3 + XC3);
    }

    // ---- out_proj z-batched -> split-bf16 concat buffer ----
    tc_gemm<128>(y3, wout3, nullptr, cat3, NROWS, DMODEL, DMODEL, 6144,
                 XC3, (size_t)DMODEL * 6144, 0, 0, 2, nullptr, nullptr,
                 2 * DMODEL, 0, DMODEL, 2);

    // ---- merge: (2048 x 1024) = cat3 @ wm3^T -> output ----
    tc_gemm<128>(cat3, wm3, out, nullptr, NROWS, DMODEL, DMODEL, 6144,
                 0, 0, 0, DMODEL, 0, nullptr, nullptr, 0, 0, 0, 1);
}